// round 6
// baseline (speedup 1.0000x reference)
#include <cuda_runtime.h>
#include <cuda_fp16.h>
#include <cstdint>

#define THREADS 256
#define XS_H 120     // xs row stride in halves (60 words; gid*60 mod 32 spans 8 groups)
#define W1_H 120
#define W2_H 72      // 36 words; gid*36 mod 32 = gid*4 -> conflict-free

// smem: xs 256*120*2=61440, w1 64*120*2=15360, w2 32*72*2=4608, b1 256, b2 128
#define SM_BYTES (61440 + 15360 + 4608 + 256 + 128)

__device__ __forceinline__ uint2 f4_to_h4(float4 v) {
    __half2 lo = __floats2half2_rn(v.x, v.y);
    __half2 hi = __floats2half2_rn(v.z, v.w);
    uint2 r;
    r.x = *(uint32_t*)&lo;
    r.y = *(uint32_t*)&hi;
    return r;
}
__device__ __forceinline__ uint32_t f2_to_h2(float x, float y) {
    __half2 h = __floats2half2_rn(x, y);
    return *(uint32_t*)&h;
}

__device__ __forceinline__ void mma_f16(float* d, const uint32_t* a, const uint32_t* b) {
    asm volatile(
        "mma.sync.aligned.m16n8k16.row.col.f32.f16.f16.f32 "
        "{%0,%1,%2,%3}, {%4,%5,%6,%7}, {%8,%9}, {%0,%1,%2,%3};"
        : "+f"(d[0]), "+f"(d[1]), "+f"(d[2]), "+f"(d[3])
        : "r"(a[0]), "r"(a[1]), "r"(a[2]), "r"(a[3]), "r"(b[0]), "r"(b[1]));
}

extern "C" __global__ void __launch_bounds__(THREADS, 2)
edge_mlp_w(const float* __restrict__ src, const float* __restrict__ dst,
           const float* __restrict__ ea, const float* __restrict__ u,
           const int* __restrict__ batch,
           const float* __restrict__ W1, const float* __restrict__ b1,
           const float* __restrict__ W2, const float* __restrict__ b2,
           float* __restrict__ out, int E, int nchunks)
{
    extern __shared__ char smraw[];
    __half* xs  = (__half*)smraw;                 // [8 warps][32 rows][XS_H]
    __half* w1s = xs + 256 * XS_H;                // [64 n][W1_H k]
    __half* w2s = w1s + 64 * W1_H;                // [32 n][W2_H k]
    float*  b1s = (float*)(w2s + 32 * W2_H);      // 64
    float*  b2s = b1s + 64;                       // 32

    const int t    = threadIdx.x;
    const int w    = t >> 5;
    const int lane = t & 31;
    const int gid  = lane >> 2;   // 0..7
    const int ctid = lane & 3;    // 0..3

    // ---- stage weights once ----
    {
        const float2* w12 = (const float2*)W1;     // 64*56
        #pragma unroll
        for (int it = 0; it < 14; it++) {
            int i = t + it * THREADS;
            int n = i / 56, k2 = i % 56;
            float2 v = w12[i];
            *(uint32_t*)&w1s[n * W1_H + 2 * k2] = f2_to_h2(v.x, v.y);
        }
        const float2* w22 = (const float2*)W2;     // 32*32
        #pragma unroll
        for (int it = 0; it < 4; it++) {
            int i = t + it * THREADS;
            int n = i / 32, k2 = i % 32;
            float2 v = w22[i];
            *(uint32_t*)&w2s[n * W2_H + 2 * k2] = f2_to_h2(v.x, v.y);
        }
        if (t < 64) b1s[t] = b1[t];
        if (t < 32) b2s[t] = b2[t];
    }
    __syncthreads();

    __half* xw = xs + w * 32 * XS_H;   // this warp's private 32-row tile
    const float4* src4 = (const float4*)src;
    const float4* dst4 = (const float4*)dst;
    const float4* ea4  = (const float4*)ea;
    const float4* u4   = (const float4*)u;

    // ---- per-warp independent chunk loop: 32 edges per chunk ----
    for (int ch = blockIdx.x * 8 + w; ch < nchunks; ch += gridDim.x * 8) {
        const int e0 = ch * 32;

        __syncwarp();   // prior chunk's xs reads done before overwrite
        // ---- stage this warp's 32 rows: row r = [src|dst|ea|u[batch]] ----
        #pragma unroll 4
        for (int r = 0; r < 32; r++) {
            int e = e0 + r;
            if (lane < 28) {
                float4 v = make_float4(0.f, 0.f, 0.f, 0.f);
                if (e < E) {
                    if (lane < 8)       v = src4[(size_t)e * 8 + lane];
                    else if (lane < 16) v = dst4[(size_t)e * 8 + lane - 8];
                    else if (lane < 24) v = ea4[(size_t)e * 8 + lane - 16];
                    else                v = u4[(size_t)batch[e] * 4 + lane - 24];
                }
                *(uint2*)&xw[r * XS_H + lane * 4] = f4_to_h4(v);
            }
        }
        __syncwarp();

        // ================= GEMM1: [32x112] @ [112x64], full N per warp =========
        float acc[2][8][4];
        #pragma unroll
        for (int mt = 0; mt < 2; mt++)
            #pragma unroll
            for (int nt = 0; nt < 8; nt++)
                #pragma unroll
                for (int q = 0; q < 4; q++) acc[mt][nt][q] = 0.f;

        #pragma unroll
        for (int ks = 0; ks < 7; ks++) {
            const int k0 = 16 * ks + 2 * ctid;
            uint32_t a[2][4];
            #pragma unroll
            for (int mt = 0; mt < 2; mt++) {
                int r0 = 16 * mt + gid;
                a[mt][0] = *(const uint32_t*)&xw[r0 * XS_H + k0];
                a[mt][1] = *(const uint32_t*)&xw[(r0 + 8) * XS_H + k0];
                a[mt][2] = *(const uint32_t*)&xw[r0 * XS_H + k0 + 8];
                a[mt][3] = *(const uint32_t*)&xw[(r0 + 8) * XS_H + k0 + 8];
            }
            #pragma unroll
            for (int nt = 0; nt < 8; nt++) {
                int n = 8 * nt + gid;
                uint32_t b[2];
                b[0] = *(const uint32_t*)&w1s[n * W1_H + k0];
                b[1] = *(const uint32_t*)&w1s[n * W1_H + k0 + 8];
                mma_f16(acc[0][nt], a[0], b);
                mma_f16(acc[1][nt], a[1], b);
            }
        }

        // ====== epilogue 1 in registers: bias+relu -> fp16 A-frags of GEMM2 =====
        // GEMM1 D layout == GEMM2 A layout (k = GEMM1 n); no smem round-trip.
        float acc2[2][4][4];
        #pragma unroll
        for (int mt = 0; mt < 2; mt++)
            #pragma unroll
            for (int nt = 0; nt < 4; nt++)
                #pragma unroll
                for (int q = 0; q < 4; q++) acc2[mt][nt][q] = 0.f;

        #pragma unroll
        for (int ks = 0; ks < 4; ks++) {
            const int k0 = 16 * ks + 2 * ctid;
            float2 bA = *(const float2*)&b1s[16 * ks + 2 * ctid];
            float2 bB = *(const float2*)&b1s[16 * ks + 8 + 2 * ctid];
            uint32_t a2[2][4];
            #pragma unroll
            for (int mt = 0; mt < 2; mt++) {
                a2[mt][0] = f2_to_h2(fmaxf(acc[mt][2*ks][0] + bA.x, 0.f),
                                     fmaxf(acc[mt][2*ks][1] + bA.y, 0.f));
                a2[mt][1] = f2_to_h2(fmaxf(acc[mt][2*ks][2] + bA.x, 0.f),
                                     fmaxf(acc[mt][2*ks][3] + bA.y, 0.f));
                a2[mt][2] = f2_to_h2(fmaxf(acc[mt][2*ks+1][0] + bB.x, 0.f),
                                     fmaxf(acc[mt][2*ks+1][1] + bB.y, 0.f));
                a2[mt][3] = f2_to_h2(fmaxf(acc[mt][2*ks+1][2] + bB.x, 0.f),
                                     fmaxf(acc[mt][2*ks+1][3] + bB.y, 0.f));
            }
            #pragma unroll
            for (int nt = 0; nt < 4; nt++) {
                int n = 8 * nt + gid;
                uint32_t b[2];
                b[0] = *(const uint32_t*)&w2s[n * W2_H + k0];
                b[1] = *(const uint32_t*)&w2s[n * W2_H + k0 + 8];
                mma_f16(acc2[0][nt], a2[0], b);
                mma_f16(acc2[1][nt], a2[1], b);
            }
        }

        // ---- epilogue 2: bias + store ----
        #pragma unroll
        for (int mt = 0; mt < 2; mt++) {
            int e = e0 + 16 * mt + gid;
            #pragma unroll
            for (int nt = 0; nt < 4; nt++) {
                int c = 8 * nt + 2 * ctid;
                float2 bv = *(const float2*)&b2s[c];
                if (e < E) {
                    float2 v;
                    v.x = acc2[mt][nt][0] + bv.x;
                    v.y = acc2[mt][nt][1] + bv.y;
                    *(float2*)&out[(size_t)e * 32 + c] = v;
                }
                if (e + 8 < E) {
                    float2 v;
                    v.x = acc2[mt][nt][2] + bv.x;
                    v.y = acc2[mt][nt][3] + bv.y;
                    *(float2*)&out[(size_t)(e + 8) * 32 + c] = v;
                }
            }
        }
    }
}

extern "C" void kernel_launch(void* const* d_in, const int* in_sizes, int n_in,
                              void* d_out, int out_size) {
    const float* src   = (const float*)d_in[0];
    const float* dst   = (const float*)d_in[1];
    const float* ea    = (const float*)d_in[2];
    const float* u     = (const float*)d_in[3];
    const int*   batch = (const int*)d_in[4];
    const float* W1    = (const float*)d_in[5];
    const float* b1    = (const float*)d_in[6];
    const float* W2    = (const float*)d_in[7];
    const float* b2    = (const float*)d_in[8];
    float*       out   = (float*)d_out;

    int E = in_sizes[0] / 32;
    int nchunks = (E + 31) / 32;

    int nsm = 148;
    cudaDeviceGetAttribute(&nsm, cudaDevAttrMultiProcessorCount, 0);
    int grid = 2 * nsm;
    int maxg = (nchunks + 7) / 8;
    if (grid > maxg) grid = maxg;

    cudaFuncSetAttribute(edge_mlp_w,
                         cudaFuncAttributeMaxDynamicSharedMemorySize, SM_BYTES);
    edge_mlp_w<<<grid, THREADS, SM_BYTES>>>(src, dst, ea, u, batch,
                                            W1, b1, W2, b2, out, E, nchunks);
}

// round 7
// speedup vs baseline: 2.7441x; 2.7441x over previous
#include <cuda_runtime.h>
#include <cuda_fp16.h>
#include <cstdint>

#define THREADS 256
#define TPC     4        // tiles per CTA
#define TILE    128
#define XS_H    120      // xs stride in halves (60 words; gid*60 mod 32 -> 8 distinct groups)
#define W1_H    120
#define HS_H    72       // h stride in halves (36 words; 4gid+ctid -> conflict-free)

// smem: xs 2*128*120*2 = 61440, w1 64*120*2 = 15360, h 128*72*2 = 18432, b 384
#define SM_BYTES (61440 + 15360 + 18432 + 384)

__device__ __forceinline__ uint2 f4_to_h4(float4 v) {
    __half2 lo = __floats2half2_rn(v.x, v.y);
    __half2 hi = __floats2half2_rn(v.z, v.w);
    uint2 r;
    r.x = *(uint32_t*)&lo;
    r.y = *(uint32_t*)&hi;
    return r;
}
__device__ __forceinline__ uint32_t f2_to_h2(float x, float y) {
    __half2 h = __floats2half2_rn(x, y);
    return *(uint32_t*)&h;
}

__device__ __forceinline__ void mma_f16(float* d, const uint32_t* a, const uint32_t* b) {
    asm volatile(
        "mma.sync.aligned.m16n8k16.row.col.f32.f16.f16.f32 "
        "{%0,%1,%2,%3}, {%4,%5,%6,%7}, {%8,%9}, {%0,%1,%2,%3};"
        : "+f"(d[0]), "+f"(d[1]), "+f"(d[2]), "+f"(d[3])
        : "r"(a[0]), "r"(a[1]), "r"(a[2]), "r"(a[3]), "r"(b[0]), "r"(b[1]));
}

extern "C" __global__ void __launch_bounds__(THREADS, 2)
edge_mlp_db(const float* __restrict__ src, const float* __restrict__ dst,
            const float* __restrict__ ea, const float* __restrict__ u,
            const int* __restrict__ batch,
            const float* __restrict__ W1, const float* __restrict__ b1,
            const float* __restrict__ W2, const float* __restrict__ b2,
            float* __restrict__ out, int E, int ntiles)
{
    extern __shared__ char smraw[];
    __half* xsA = (__half*)smraw;                 // [128][XS_H]
    __half* xsB = xsA + 128 * XS_H;               // [128][XS_H]
    __half* w1s = xsB + 128 * XS_H;               // [64 n][W1_H k]
    __half* hsm = w1s + 64 * W1_H;                // [128][HS_H]
    float*  b1s = (float*)(hsm + 128 * HS_H);     // 64
    float*  b2s = b1s + 64;                       // 32

    const int t    = threadIdx.x;
    const int w    = t >> 5;
    const int lane = t & 31;
    const int gid  = lane >> 2;     // 0..7
    const int ctid = lane & 3;      // 0..3
    const int mbase = (w & 3) * 32;
    const int nbase = (w >> 2) * 32;   // GEMM1 N slice
    const int nb2   = (w >> 2) * 16;   // GEMM2 N slice

    // ---- stage W1 as [n][k] halves ----
    {
        const float2* w12 = (const float2*)W1;     // 64*56 float2
        #pragma unroll
        for (int it = 0; it < 14; it++) {
            int i = t + it * THREADS;
            int n = i / 56, k2 = i % 56;
            float2 v = w12[i];
            *(uint32_t*)&w1s[n * W1_H + 2 * k2] = f2_to_h2(v.x, v.y);
        }
        if (t < 64) b1s[t] = b1[t];
        if (t < 32) b2s[t] = b2[t];
    }

    // ---- W2 fragments persist in registers ----
    uint32_t w2r[4][2][2];   // [ks][nt][b0/b1]
    #pragma unroll
    for (int ks = 0; ks < 4; ks++)
        #pragma unroll
        for (int nt = 0; nt < 2; nt++) {
            int n  = nb2 + 8 * nt + gid;
            int k0 = 16 * ks + 2 * ctid;
            float2 v0 = *(const float2*)&W2[n * 64 + k0];
            float2 v1 = *(const float2*)&W2[n * 64 + k0 + 8];
            w2r[ks][nt][0] = f2_to_h2(v0.x, v0.y);
            w2r[ks][nt][1] = f2_to_h2(v1.x, v1.y);
        }

    const float4* src4 = (const float4*)src;
    const float4* dst4 = (const float4*)dst;
    const float4* ea4  = (const float4*)ea;
    const float4* u4   = (const float4*)u;

    // ---- cooperative tile staging: [128][112] halves = [src|dst|ea|u[batch]] ----
    auto stage_x = [&](__half* buf, int tile_idx) {
        const int e0 = tile_idx * TILE;
        #pragma unroll
        for (int blk = 0; blk < 3; blk++) {
            const float4* a4 = (blk == 0) ? src4 : (blk == 1) ? dst4 : ea4;
            #pragma unroll
            for (int it = 0; it < 4; it++) {
                int r = (t >> 3) + 32 * it, c = t & 7;
                int e = e0 + r;
                float4 v = make_float4(0.f, 0.f, 0.f, 0.f);
                if (e < E) v = a4[(size_t)e * 8 + c];
                *(uint2*)&buf[r * XS_H + blk * 32 + c * 4] = f4_to_h4(v);
            }
        }
        #pragma unroll
        for (int it = 0; it < 2; it++) {
            int r = (t >> 2) + 64 * it, c = t & 3;
            int e = e0 + r;
            float4 v = make_float4(0.f, 0.f, 0.f, 0.f);
            if (e < E) { int bi = batch[e]; v = u4[(size_t)bi * 4 + c]; }
            *(uint2*)&buf[r * XS_H + 96 + c * 4] = f4_to_h4(v);
        }
    };

    const int tile0 = blockIdx.x * TPC;
    if (tile0 < ntiles) stage_x(xsA, tile0);
    __syncthreads();

    #pragma unroll 1
    for (int j = 0; j < TPC; j++) {
        const int tile = tile0 + j;
        if (tile >= ntiles) break;
        const int e0 = tile * TILE;
        __half* cur = (j & 1) ? xsB : xsA;
        __half* nxt = (j & 1) ? xsA : xsB;

        // ---- prefetch next tile (LDGs issued before compute; STS drain at mid barrier) ----
        if (j + 1 < TPC && tile + 1 < ntiles) stage_x(nxt, tile + 1);

        // ================= GEMM1: [128x112] @ [112x64], fp16 mma =================
        float acc[2][4][4];
        #pragma unroll
        for (int mt = 0; mt < 2; mt++)
            #pragma unroll
            for (int nt = 0; nt < 4; nt++)
                #pragma unroll
                for (int q = 0; q < 4; q++) acc[mt][nt][q] = 0.f;

        #pragma unroll
        for (int ks = 0; ks < 7; ks++) {
            const int k0 = 16 * ks + 2 * ctid;
            uint32_t a[2][4], b[4][2];
            #pragma unroll
            for (int mt = 0; mt < 2; mt++) {
                int r0 = mbase + 16 * mt + gid;
                a[mt][0] = *(const uint32_t*)&cur[r0 * XS_H + k0];
                a[mt][1] = *(const uint32_t*)&cur[(r0 + 8) * XS_H + k0];
                a[mt][2] = *(const uint32_t*)&cur[r0 * XS_H + k0 + 8];
                a[mt][3] = *(const uint32_t*)&cur[(r0 + 8) * XS_H + k0 + 8];
            }
            #pragma unroll
            for (int nt = 0; nt < 4; nt++) {
                int n = nbase + 8 * nt + gid;
                b[nt][0] = *(const uint32_t*)&w1s[n * W1_H + k0];
                b[nt][1] = *(const uint32_t*)&w1s[n * W1_H + k0 + 8];
            }
            #pragma unroll
            for (int mt = 0; mt < 2; mt++)
                #pragma unroll
                for (int nt = 0; nt < 4; nt++)
                    mma_f16(acc[mt][nt], a[mt], b[nt]);
        }

        // ---- epilogue 1: bias + relu -> h halves (separate region) ----
        #pragma unroll
        for (int mt = 0; mt < 2; mt++) {
            int r0 = mbase + 16 * mt + gid;
            #pragma unroll
            for (int nt = 0; nt < 4; nt++) {
                int c = nbase + 8 * nt + 2 * ctid;
                float bx = b1s[c], by = b1s[c + 1];
                *(uint32_t*)&hsm[r0 * HS_H + c] =
                    f2_to_h2(fmaxf(acc[mt][nt][0] + bx, 0.f),
                             fmaxf(acc[mt][nt][1] + by, 0.f));
                *(uint32_t*)&hsm[(r0 + 8) * HS_H + c] =
                    f2_to_h2(fmaxf(acc[mt][nt][2] + bx, 0.f),
                             fmaxf(acc[mt][nt][3] + by, 0.f));
            }
        }
        __syncthreads();   // h visible to consumers; staging STS drained

        // ================= GEMM2: [128x64] @ [64x32], B in registers =================
        float acc2[2][2][4];
        #pragma unroll
        for (int mt = 0; mt < 2; mt++)
            #pragma unroll
            for (int nt = 0; nt < 2; nt++)
                #pragma unroll
                for (int q = 0; q < 4; q++) acc2[mt][nt][q] = 0.f;

        #pragma unroll
        for (int ks = 0; ks < 4; ks++) {
            const int k0 = 16 * ks + 2 * ctid;
            uint32_t a[2][4];
            #pragma unroll
            for (int mt = 0; mt < 2; mt++) {
                int r0 = mbase + 16 * mt + gid;
                a[mt][0] = *(const uint32_t*)&hsm[r0 * HS_H + k0];
                a[mt][1] = *(const uint32_t*)&hsm[(r0 + 8) * HS_H + k0];
                a[mt][2] = *(const uint32_t*)&hsm[r0 * HS_H + k0 + 8];
                a[mt][3] = *(const uint32_t*)&hsm[(r0 + 8) * HS_H + k0 + 8];
            }
            #pragma unroll
            for (int mt = 0; mt < 2; mt++)
                #pragma unroll
                for (int nt = 0; nt < 2; nt++)
                    mma_f16(acc2[mt][nt], a[mt], w2r[ks][nt]);
        }

        // ---- epilogue 2: bias + store to gmem ----
        #pragma unroll
        for (int mt = 0; mt < 2; mt++) {
            int e = e0 + mbase + 16 * mt + gid;
            #pragma unroll
            for (int nt = 0; nt < 2; nt++) {
                int c = nb2 + 8 * nt + 2 * ctid;
                float bx = b2s[c], by = b2s[c + 1];
                if (e < E) {
                    float2 v; v.x = acc2[mt][nt][0] + bx; v.y = acc2[mt][nt][1] + by;
                    *(float2*)&out[(size_t)e * 32 + c] = v;
                }
                if (e + 8 < E) {
                    float2 v; v.x = acc2[mt][nt][2] + bx; v.y = acc2[mt][nt][3] + by;
                    *(float2*)&out[(size_t)(e + 8) * 32 + c] = v;
                }
            }
        }
        __syncthreads();   // h readers done before next tile overwrites h
    }
}

extern "C" void kernel_launch(void* const* d_in, const int* in_sizes, int n_in,
                              void* d_out, int out_size) {
    const float* src   = (const float*)d_in[0];
    const float* dst   = (const float*)d_in[1];
    const float* ea    = (const float*)d_in[2];
    const float* u     = (const float*)d_in[3];
    const int*   batch = (const int*)d_in[4];
    const float* W1    = (const float*)d_in[5];
    const float* b1    = (const float*)d_in[6];
    const float* W2    = (const float*)d_in[7];
    const float* b2    = (const float*)d_in[8];
    float*       out   = (float*)d_out;

    int E = in_sizes[0] / 32;
    int ntiles = (E + TILE - 1) / TILE;
    int grid = (ntiles + TPC - 1) / TPC;

    cudaFuncSetAttribute(edge_mlp_db,
                         cudaFuncAttributeMaxDynamicSharedMemorySize, SM_BYTES);
    edge_mlp_db<<<grid, THREADS, SM_BYTES>>>(src, dst, ea, u, batch,
                                             W1, b1, W2, b2, out, E, ntiles);
}